// round 3
// baseline (speedup 1.0000x reference)
#include <cuda_runtime.h>
#include <math.h>

#define NN   100000
#define EE   1600000
#define DIM  128

// Scratch (static device globals: no allocations allowed)
__device__ float g_dis[NN];
__device__ float g_h [(size_t)NN * DIM];   // hs of layer 0 / layer 2
__device__ float g_h2[(size_t)NN * DIM];   // hs of layer 1
__device__ float g_a [(size_t)NN * DIM];   // agg of layer 0 / layer 2
__device__ float g_b [(size_t)NN * DIM];   // agg of layer 1

__device__ __forceinline__ void red_add_v4(float* addr, float x, float y, float z, float w) {
    asm volatile("red.global.add.v4.f32 [%0], {%1, %2, %3, %4};"
                 :: "l"(addr), "f"(x), "f"(y), "f"(z), "f"(w) : "memory");
}

// ---------------------------------------------------------------------------
// Degree / normalization
// ---------------------------------------------------------------------------
__global__ void init_dis_kernel(float* dis, int n) {
    int i = blockIdx.x * blockDim.x + threadIdx.x;
    if (i < n) dis[i] = 1.0f;  // self-loop contributes 1 to degree
}

__global__ void deg_kernel(const int* __restrict__ dst, float* dis, int e) {
    int i = blockIdx.x * blockDim.x + threadIdx.x;
    if (i < e) atomicAdd(&dis[dst[i]], 1.0f);
}

__global__ void rsqrt_kernel(float* dis, int n) {
    int i = blockIdx.x * blockDim.x + threadIdx.x;
    if (i < n) dis[i] = rsqrtf(dis[i]);
}

// ---------------------------------------------------------------------------
// Fused GEMM:
//   MODE 0: A = X                              (layer 0 input)
//   MODE 1: A = relu(dis[r]*(AGG[r]+HS[r]) + BP)   (combine of previous layer)
//   C = A @ W   ;   hs_out = C * dis[row]   ;   agg_next = 0
// BM=128, BK=16, 256 threads, 8xTN micro-tile (TN = BN/16).
// Previous-layer width is always 128 (A-side stride hardcoded).
// ---------------------------------------------------------------------------
template <int BN, int MODE>
__global__ __launch_bounds__(256) void gemm_kernel(
    const float* __restrict__ X,
    const float* __restrict__ AGG,
    const float* __restrict__ HS,
    const float* __restrict__ BP,
    const float* __restrict__ W,
    const float* __restrict__ dis,
    float* __restrict__ hs_out,
    float* __restrict__ agg_next,
    int M)
{
    constexpr int TN = BN / 16;          // 8 or 4
    constexpr int NB = (16 * BN) / 1024; // B float4 loads per thread (2 or 1)

    __shared__ float As[16][128];
    __shared__ float Bs[16][BN];

    const int tid  = threadIdx.x;
    const int tx   = tid & 15;
    const int ty   = tid >> 4;
    const int row0 = blockIdx.x * 128;
    const int lr   = tid >> 2;        // 0..63
    const int lk   = (tid & 3) * 4;   // 0,4,8,12

    float acc[8][TN];
#pragma unroll
    for (int i = 0; i < 8; i++)
#pragma unroll
        for (int j = 0; j < TN; j++) acc[i][j] = 0.f;

    float4 nA[2];
    float4 nB[NB];

    auto loadA = [&](int k0, int rr) -> float4 {
        int arow = row0 + rr;
        float4 v = make_float4(0.f, 0.f, 0.f, 0.f);
        if (arow < M) {
            if (MODE == 0) {
                v = *(const float4*)(X + (size_t)arow * 128 + k0 + lk);
            } else {
                float  dd = __ldg(dis + arow);
                float4 ag = *(const float4*)(AGG + (size_t)arow * 128 + k0 + lk);
                float4 hh = *(const float4*)(HS  + (size_t)arow * 128 + k0 + lk);
                float4 bb = *(const float4*)(BP + k0 + lk);
                v.x = fmaxf(fmaf(dd, ag.x + hh.x, bb.x), 0.f);
                v.y = fmaxf(fmaf(dd, ag.y + hh.y, bb.y), 0.f);
                v.z = fmaxf(fmaf(dd, ag.z + hh.z, bb.z), 0.f);
                v.w = fmaxf(fmaf(dd, ag.w + hh.w, bb.w), 0.f);
            }
        }
        return v;
    };

    auto fetch = [&](int k0) {
        nA[0] = loadA(k0, lr);
        nA[1] = loadA(k0, lr + 64);
#pragma unroll
        for (int t = 0; t < NB; t++) {
            int f4 = tid + t * 256;
            int kk = f4 / (BN / 4);
            int jj = (f4 % (BN / 4)) * 4;
            nB[t] = *(const float4*)(W + (size_t)(k0 + kk) * BN + jj);
        }
    };

    auto stage = [&]() {
        As[lk + 0][lr] = nA[0].x; As[lk + 1][lr] = nA[0].y;
        As[lk + 2][lr] = nA[0].z; As[lk + 3][lr] = nA[0].w;
        As[lk + 0][lr + 64] = nA[1].x; As[lk + 1][lr + 64] = nA[1].y;
        As[lk + 2][lr + 64] = nA[1].z; As[lk + 3][lr + 64] = nA[1].w;
#pragma unroll
        for (int t = 0; t < NB; t++) {
            int f4 = tid + t * 256;
            int kk = f4 / (BN / 4);
            int jj = (f4 % (BN / 4)) * 4;
            *(float4*)&Bs[kk][jj] = nB[t];
        }
    };

    fetch(0);
    stage();
    __syncthreads();

    for (int chunk = 0; chunk < 8; chunk++) {
        if (chunk < 7) fetch((chunk + 1) * 16);

#pragma unroll
        for (int k = 0; k < 16; k++) {
            float4 a0 = *(const float4*)&As[k][ty * 8];
            float4 a1 = *(const float4*)&As[k][ty * 8 + 4];
            float a[8] = {a0.x, a0.y, a0.z, a0.w, a1.x, a1.y, a1.z, a1.w};
            float b[TN];
#pragma unroll
            for (int j = 0; j < TN; j += 4) {
                float4 bt = *(const float4*)&Bs[k][tx * TN + j];
                b[j] = bt.x; b[j + 1] = bt.y; b[j + 2] = bt.z; b[j + 3] = bt.w;
            }
#pragma unroll
            for (int i = 0; i < 8; i++)
#pragma unroll
                for (int j = 0; j < TN; j++)
                    acc[i][j] = fmaf(a[i], b[j], acc[i][j]);
        }

        __syncthreads();
        if (chunk < 7) {
            stage();
            __syncthreads();
        }
    }

    // Epilogue: hs_out = acc * dis[row]; agg_next = 0 (ready for scatter)
#pragma unroll
    for (int i = 0; i < 8; i++) {
        int row = row0 + ty * 8 + i;
        if (row < M) {
            float dd = __ldg(dis + row);
#pragma unroll
            for (int j = 0; j < TN; j += 4) {
                float4 o = make_float4(acc[i][j] * dd, acc[i][j + 1] * dd,
                                       acc[i][j + 2] * dd, acc[i][j + 3] * dd);
                *(float4*)(hs_out   + (size_t)row * BN + tx * TN + j) = o;
                *(float4*)(agg_next + (size_t)row * BN + tx * TN + j) =
                    make_float4(0.f, 0.f, 0.f, 0.f);
            }
        }
    }
}

// ---------------------------------------------------------------------------
// agg[dst,:] += hs[src,:]   (pure vector red.global.add.v4, no norm loads)
// ---------------------------------------------------------------------------
template <int F>
__global__ void scatter_kernel(const float* __restrict__ hs, const int* __restrict__ src,
                               const int* __restrict__ dst, float* __restrict__ agg, int e) {
    constexpr int Q = F / 4;
    int tid = blockIdx.x * blockDim.x + threadIdx.x;
    if (tid >= e * Q) return;
    int ed = tid / Q;
    int q  = (tid % Q) * 4;
    int s  = __ldg(src + ed);
    int d  = __ldg(dst + ed);
    float4 v = *(const float4*)(hs + (size_t)s * F + q);
    red_add_v4(agg + (size_t)d * F + q, v.x, v.y, v.z, v.w);
}

// ---------------------------------------------------------------------------
// out = log_softmax(relu(dis*(agg+hs)+b), axis=1)  -- 64 cols, warp per node
// ---------------------------------------------------------------------------
__global__ void logsoftmax_kernel(const float* __restrict__ agg, const float* __restrict__ hs,
                                  const float* __restrict__ bias, const float* __restrict__ dis,
                                  float* __restrict__ out, int n) {
    int gtid = blockIdx.x * blockDim.x + threadIdx.x;
    int warp = gtid >> 5;
    int lane = gtid & 31;
    if (warp >= n) return;
    float dd = __ldg(dis + warp);
    const float* arow = agg + (size_t)warp * 64;
    const float* hrow = hs  + (size_t)warp * 64;
    float v0 = fmaxf(fmaf(dd, arow[lane]      + hrow[lane],      bias[lane]),      0.f);
    float v1 = fmaxf(fmaf(dd, arow[lane + 32] + hrow[lane + 32], bias[lane + 32]), 0.f);
    float m = fmaxf(v0, v1);
#pragma unroll
    for (int off = 16; off > 0; off >>= 1)
        m = fmaxf(m, __shfl_xor_sync(0xffffffffu, m, off));
    float s = expf(v0 - m) + expf(v1 - m);
#pragma unroll
    for (int off = 16; off > 0; off >>= 1)
        s += __shfl_xor_sync(0xffffffffu, s, off);
    float ls = logf(s);
    float* orow = out + (size_t)warp * 64;
    orow[lane]      = v0 - m - ls;
    orow[lane + 32] = v1 - m - ls;
}

// ---------------------------------------------------------------------------
// Launch
// ---------------------------------------------------------------------------
extern "C" void kernel_launch(void* const* d_in, const int* in_sizes, int n_in,
                              void* d_out, int out_size) {
    const float* x  = (const float*)d_in[0];
    const int*   ei = (const int*)d_in[1];
    const float* W0 = (const float*)d_in[2];
    const float* b0 = (const float*)d_in[3];
    const float* W1 = (const float*)d_in[4];
    const float* b1 = (const float*)d_in[5];
    const float* W2 = (const float*)d_in[6];
    const float* b2 = (const float*)d_in[7];
    float* out = (float*)d_out;

    const int E = in_sizes[1] / 2;
    const int N = in_sizes[0] / DIM;
    const int* src = ei;
    const int* dst = ei + E;

    float *p_dis, *p_h, *p_h2, *p_a, *p_b;
    cudaGetSymbolAddress((void**)&p_dis, g_dis);
    cudaGetSymbolAddress((void**)&p_h,   g_h);
    cudaGetSymbolAddress((void**)&p_h2,  g_h2);
    cudaGetSymbolAddress((void**)&p_a,   g_a);
    cudaGetSymbolAddress((void**)&p_b,   g_b);

    const int T = 256;
    const int gemm_blocks = (N + 127) / 128;

    // Degree / symmetric normalization
    init_dis_kernel<<<(N + T - 1) / T, T>>>(p_dis, N);
    deg_kernel<<<(E + T - 1) / T, T>>>(dst, p_dis, E);
    rsqrt_kernel<<<(N + T - 1) / T, T>>>(p_dis, N);

    // Layer 0:  hs0 = (x@W0)*dis   ; agg0 zeroed ; scatter -> agg0
    gemm_kernel<128, 0><<<gemm_blocks, 256>>>(x, nullptr, nullptr, nullptr,
                                              W0, p_dis, p_h, p_a, N);
    scatter_kernel<128><<<((size_t)E * 32 + T - 1) / T, T>>>(p_h, src, dst, p_a, E);

    // Layer 1:  A = relu(dis*(agg0+hs0)+b0) ; hs1 ; agg1 zeroed ; scatter -> agg1
    gemm_kernel<128, 1><<<gemm_blocks, 256>>>(nullptr, p_a, p_h, b0,
                                              W1, p_dis, p_h2, p_b, N);
    scatter_kernel<128><<<((size_t)E * 32 + T - 1) / T, T>>>(p_h2, src, dst, p_b, E);

    // Layer 2 (64 cols): A = relu(dis*(agg1+hs1)+b1) ; hs2 ; agg2 zeroed ; scatter
    gemm_kernel<64, 1><<<gemm_blocks, 256>>>(nullptr, p_b, p_h2, b1,
                                             W2, p_dis, p_h, p_a, N);
    scatter_kernel<64><<<((size_t)E * 16 + T - 1) / T, T>>>(p_h, src, dst, p_a, E);

    // out = log_softmax(relu(dis*(agg2+hs2)+b2))
    logsoftmax_kernel<<<(N * 32 + T - 1) / T, T>>>(p_a, p_h, b2, p_dis, out, N);
}

// round 4
// speedup vs baseline: 1.3319x; 1.3319x over previous
#include <cuda_runtime.h>
#include <math.h>

#define NN   100000
#define EE   1600000
#define DIM  128

// Scratch (static device globals: no allocations allowed)
__device__ float g_dis[NN];
__device__ float g_h [(size_t)NN * DIM];   // hs of layer 0 / layer 2
__device__ float g_h2[(size_t)NN * DIM];   // hs of layer 1
__device__ float g_a [(size_t)NN * DIM];   // agg of layer 0 / layer 2
__device__ float g_b [(size_t)NN * DIM];   // agg of layer 1

__device__ __forceinline__ void red_add_v4(float* addr, float x, float y, float z, float w) {
    asm volatile("red.global.add.v4.f32 [%0], {%1, %2, %3, %4};"
                 :: "l"(addr), "f"(x), "f"(y), "f"(z), "f"(w) : "memory");
}

// ---------------------------------------------------------------------------
// Degree / normalization
// ---------------------------------------------------------------------------
__global__ void init_dis_kernel(float* dis, int n) {
    int i = blockIdx.x * blockDim.x + threadIdx.x;
    if (i < n) dis[i] = 1.0f;  // self-loop contributes 1 to degree
}

__global__ void deg_kernel(const int* __restrict__ dst, float* dis, int e) {
    int i = blockIdx.x * blockDim.x + threadIdx.x;
    if (i < e) atomicAdd(&dis[dst[i]], 1.0f);
}

__global__ void rsqrt_kernel(float* dis, int n) {
    int i = blockIdx.x * blockDim.x + threadIdx.x;
    if (i < n) dis[i] = rsqrtf(dis[i]);
}

// ---------------------------------------------------------------------------
// Fused GEMM (round-2 shape: BM=64, 256 threads, 4 x TN micro-tile):
//   MODE 0: A = X
//   MODE 1: A = relu(dis[r]*(AGG[r]+HS[r]) + BP)   (combine of previous layer)
//   C = A @ W   ;   hs_out = C * dis[row]   ;   agg_next = 0
// ---------------------------------------------------------------------------
template <int BN, int MODE>
__global__ __launch_bounds__(256) void gemm_kernel(
    const float* __restrict__ X,
    const float* __restrict__ AGG,
    const float* __restrict__ HS,
    const float* __restrict__ BP,
    const float* __restrict__ W,
    const float* __restrict__ dis,
    float* __restrict__ hs_out,
    float* __restrict__ agg_next,
    int M)
{
    constexpr int TN = BN / 16;
    __shared__ float As[16][64];   // As[k][m]
    __shared__ float Bs[16][BN];   // Bs[k][n]

    const int tid  = threadIdx.x;
    const int tx   = tid & 15;     // column group
    const int ty   = tid >> 4;     // row group
    const int row0 = blockIdx.x * 64;

    float acc[4][TN];
#pragma unroll
    for (int i = 0; i < 4; i++)
#pragma unroll
        for (int j = 0; j < TN; j++) acc[i][j] = 0.f;

    const int lr   = tid >> 2;        // 0..63 : row within tile for A load
    const int lk   = (tid & 3) * 4;   // 0,4,8,12 : k offset for A load
    const int arow = row0 + lr;

    for (int k0 = 0; k0 < 128; k0 += 16) {
        float4 av = make_float4(0.f, 0.f, 0.f, 0.f);
        if (arow < M) {
            if (MODE == 0) {
                av = *(const float4*)(X + (size_t)arow * 128 + k0 + lk);
            } else {
                float  dd = __ldg(dis + arow);
                float4 ag = *(const float4*)(AGG + (size_t)arow * 128 + k0 + lk);
                float4 hh = *(const float4*)(HS  + (size_t)arow * 128 + k0 + lk);
                float4 bb = *(const float4*)(BP + k0 + lk);
                av.x = fmaxf(fmaf(dd, ag.x + hh.x, bb.x), 0.f);
                av.y = fmaxf(fmaf(dd, ag.y + hh.y, bb.y), 0.f);
                av.z = fmaxf(fmaf(dd, ag.z + hh.z, bb.z), 0.f);
                av.w = fmaxf(fmaf(dd, ag.w + hh.w, bb.w), 0.f);
            }
        }
        As[lk + 0][lr] = av.x; As[lk + 1][lr] = av.y;
        As[lk + 2][lr] = av.z; As[lk + 3][lr] = av.w;

#pragma unroll
        for (int t = 0; t < (16 * BN) / 1024; t++) {
            int f4 = tid + t * 256;          // float4 index in 16 x BN tile
            int kk = f4 / (BN / 4);
            int jj = (f4 % (BN / 4)) * 4;
            *(float4*)&Bs[kk][jj] = *(const float4*)(W + (size_t)(k0 + kk) * BN + jj);
        }
        __syncthreads();

#pragma unroll
        for (int k = 0; k < 16; k++) {
            float4 at = *(const float4*)&As[k][ty * 4];
            float a[4] = {at.x, at.y, at.z, at.w};
            float b[TN];
#pragma unroll
            for (int j = 0; j < TN; j += 4) {
                float4 bt = *(const float4*)&Bs[k][tx * TN + j];
                b[j] = bt.x; b[j + 1] = bt.y; b[j + 2] = bt.z; b[j + 3] = bt.w;
            }
#pragma unroll
            for (int i = 0; i < 4; i++)
#pragma unroll
                for (int j = 0; j < TN; j++)
                    acc[i][j] = fmaf(a[i], b[j], acc[i][j]);
        }
        __syncthreads();
    }

    // Epilogue: hs_out = acc * dis[row]; agg_next = 0 (ready for scatter)
#pragma unroll
    for (int i = 0; i < 4; i++) {
        int row = row0 + ty * 4 + i;
        if (row < M) {
            float dd = __ldg(dis + row);
#pragma unroll
            for (int j = 0; j < TN; j += 4) {
                float4 o = make_float4(acc[i][j] * dd, acc[i][j + 1] * dd,
                                       acc[i][j + 2] * dd, acc[i][j + 3] * dd);
                *(float4*)(hs_out   + (size_t)row * BN + tx * TN + j) = o;
                *(float4*)(agg_next + (size_t)row * BN + tx * TN + j) =
                    make_float4(0.f, 0.f, 0.f, 0.f);
            }
        }
    }
}

// ---------------------------------------------------------------------------
// agg[dst,:] += hs[src,:]   (pure vector red.global.add.v4, no norm loads)
// ---------------------------------------------------------------------------
template <int F>
__global__ void scatter_kernel(const float* __restrict__ hs, const int* __restrict__ src,
                               const int* __restrict__ dst, float* __restrict__ agg, int e) {
    constexpr int Q = F / 4;
    int tid = blockIdx.x * blockDim.x + threadIdx.x;
    if (tid >= e * Q) return;
    int ed = tid / Q;
    int q  = (tid % Q) * 4;
    int s  = __ldg(src + ed);
    int d  = __ldg(dst + ed);
    float4 v = *(const float4*)(hs + (size_t)s * F + q);
    red_add_v4(agg + (size_t)d * F + q, v.x, v.y, v.z, v.w);
}

// ---------------------------------------------------------------------------
// out = log_softmax(relu(dis*(agg+hs)+b), axis=1)  -- 64 cols, warp per node
// ---------------------------------------------------------------------------
__global__ void logsoftmax_kernel(const float* __restrict__ agg, const float* __restrict__ hs,
                                  const float* __restrict__ bias, const float* __restrict__ dis,
                                  float* __restrict__ out, int n) {
    int gtid = blockIdx.x * blockDim.x + threadIdx.x;
    int warp = gtid >> 5;
    int lane = gtid & 31;
    if (warp >= n) return;
    float dd = __ldg(dis + warp);
    const float* arow = agg + (size_t)warp * 64;
    const float* hrow = hs  + (size_t)warp * 64;
    float v0 = fmaxf(fmaf(dd, arow[lane]      + hrow[lane],      bias[lane]),      0.f);
    float v1 = fmaxf(fmaf(dd, arow[lane + 32] + hrow[lane + 32], bias[lane + 32]), 0.f);
    float m = fmaxf(v0, v1);
#pragma unroll
    for (int off = 16; off > 0; off >>= 1)
        m = fmaxf(m, __shfl_xor_sync(0xffffffffu, m, off));
    float s = expf(v0 - m) + expf(v1 - m);
#pragma unroll
    for (int off = 16; off > 0; off >>= 1)
        s += __shfl_xor_sync(0xffffffffu, s, off);
    float ls = logf(s);
    float* orow = out + (size_t)warp * 64;
    orow[lane]      = v0 - m - ls;
    orow[lane + 32] = v1 - m - ls;
}

// ---------------------------------------------------------------------------
// Launch
// ---------------------------------------------------------------------------
extern "C" void kernel_launch(void* const* d_in, const int* in_sizes, int n_in,
                              void* d_out, int out_size) {
    const float* x  = (const float*)d_in[0];
    const int*   ei = (const int*)d_in[1];
    const float* W0 = (const float*)d_in[2];
    const float* b0 = (const float*)d_in[3];
    const float* W1 = (const float*)d_in[4];
    const float* b1 = (const float*)d_in[5];
    const float* W2 = (const float*)d_in[6];
    const float* b2 = (const float*)d_in[7];
    float* out = (float*)d_out;

    const int E = in_sizes[1] / 2;
    const int N = in_sizes[0] / DIM;
    const int* src = ei;
    const int* dst = ei + E;

    float *p_dis, *p_h, *p_h2, *p_a, *p_b;
    cudaGetSymbolAddress((void**)&p_dis, g_dis);
    cudaGetSymbolAddress((void**)&p_h,   g_h);
    cudaGetSymbolAddress((void**)&p_h2,  g_h2);
    cudaGetSymbolAddress((void**)&p_a,   g_a);
    cudaGetSymbolAddress((void**)&p_b,   g_b);

    const int T = 256;
    const int gemm_blocks = (N + 63) / 64;

    // Degree / symmetric normalization
    init_dis_kernel<<<(N + T - 1) / T, T>>>(p_dis, N);
    deg_kernel<<<(E + T - 1) / T, T>>>(dst, p_dis, E);
    rsqrt_kernel<<<(N + T - 1) / T, T>>>(p_dis, N);

    // Layer 0:  hs0 = (x@W0)*dis ; agg0 zeroed ; scatter -> agg0
    gemm_kernel<128, 0><<<gemm_blocks, 256>>>(x, nullptr, nullptr, nullptr,
                                              W0, p_dis, p_h, p_a, N);
    scatter_kernel<128><<<((size_t)E * 32 + T - 1) / T, T>>>(p_h, src, dst, p_a, E);

    // Layer 1:  A = relu(dis*(agg0+hs0)+b0) ; hs1 ; agg1 zeroed ; scatter -> agg1
    gemm_kernel<128, 1><<<gemm_blocks, 256>>>(nullptr, p_a, p_h, b0,
                                              W1, p_dis, p_h2, p_b, N);
    scatter_kernel<128><<<((size_t)E * 32 + T - 1) / T, T>>>(p_h2, src, dst, p_b, E);

    // Layer 2 (64 cols): A = relu(dis*(agg1+hs1)+b1) ; hs2 ; agg2 zeroed ; scatter
    gemm_kernel<64, 1><<<gemm_blocks, 256>>>(nullptr, p_b, p_h2, b1,
                                             W2, p_dis, p_h, p_a, N);
    scatter_kernel<64><<<((size_t)E * 16 + T - 1) / T, T>>>(p_h, src, dst, p_a, E);

    // out = log_softmax(relu(dis*(agg2+hs2)+b2))
    logsoftmax_kernel<<<(N * 32 + T - 1) / T, T>>>(p_a, p_h, b2, p_dis, out, N);
}

// round 5
// speedup vs baseline: 1.5956x; 1.1980x over previous
#include <cuda_runtime.h>
#include <math.h>

#define NN   100000
#define EE   1600000
#define DIM  128

// Scratch (static device globals: no allocations allowed)
__device__ float g_dis[NN];
__device__ float g_h [(size_t)NN * DIM];   // hs = (A@W)*dis of current layer
__device__ float g_a [(size_t)NN * DIM];   // combined activation (next layer input)
__device__ int   g_cnt[NN];                // in-degree histogram
__device__ int   g_rowptr[NN + 1];         // CSR row pointers (by dst)
__device__ int   g_cursor[NN];             // fill cursors
__device__ int   g_colsrc[EE];             // src node id per CSR slot

// ---------------------------------------------------------------------------
// init: dis = 1 (self-loop), cnt = 0
// ---------------------------------------------------------------------------
__global__ void init_kernel(float* dis, int* cnt, int n) {
    int i = blockIdx.x * blockDim.x + threadIdx.x;
    if (i < n) { dis[i] = 1.0f; cnt[i] = 0; }
}

// degree (float, for normalization) + in-degree histogram (int, for CSR)
__global__ void count_kernel(const int* __restrict__ dst, float* dis, int* cnt, int e) {
    int i = blockIdx.x * blockDim.x + threadIdx.x;
    if (i < e) {
        int d = dst[i];
        atomicAdd(&dis[d], 1.0f);
        atomicAdd(&cnt[d], 1);
    }
}

__global__ void rsqrt_kernel(float* dis, int n) {
    int i = blockIdx.x * blockDim.x + threadIdx.x;
    if (i < n) dis[i] = rsqrtf(dis[i]);
}

// ---------------------------------------------------------------------------
// Single-block exclusive scan over cnt -> rowptr (n up to a few 100K)
// ---------------------------------------------------------------------------
__global__ __launch_bounds__(1024) void scan_kernel(const int* __restrict__ cnt,
                                                    int* __restrict__ rowptr, int n) {
    __shared__ int wsum[32];
    __shared__ int carry_s;
    const int tid = threadIdx.x, lane = tid & 31, wid = tid >> 5;
    if (tid == 0) carry_s = 0;
    __syncthreads();
    for (int base = 0; base < n; base += 1024) {
        int i = base + tid;
        int v = (i < n) ? cnt[i] : 0;
        int x = v;
#pragma unroll
        for (int off = 1; off < 32; off <<= 1) {
            int t = __shfl_up_sync(0xffffffffu, x, off);
            if (lane >= off) x += t;
        }
        if (lane == 31) wsum[wid] = x;
        __syncthreads();
        if (wid == 0) {
            int w = wsum[lane];
#pragma unroll
            for (int off = 1; off < 32; off <<= 1) {
                int t = __shfl_up_sync(0xffffffffu, w, off);
                if (lane >= off) w += t;
            }
            wsum[lane] = w;
        }
        __syncthreads();
        int incl  = x + (wid ? wsum[wid - 1] : 0);
        int carry = carry_s;
        if (i < n) rowptr[i] = carry + incl - v;   // exclusive
        int total = wsum[31];
        __syncthreads();
        if (tid == 0) carry_s = carry + total;
        __syncthreads();
    }
    if (threadIdx.x == 0) rowptr[n] = carry_s;
}

__global__ void copy_cursor_kernel(const int* __restrict__ rowptr, int* __restrict__ cur, int n) {
    int i = blockIdx.x * blockDim.x + threadIdx.x;
    if (i < n) cur[i] = rowptr[i];
}

// colsrc[slot] = src, grouped by dst
__global__ void fill_kernel(const int* __restrict__ src, const int* __restrict__ dst,
                            int* __restrict__ cur, int* __restrict__ colsrc, int e) {
    int i = blockIdx.x * blockDim.x + threadIdx.x;
    if (i < e) {
        int pos = atomicAdd(&cur[dst[i]], 1);
        colsrc[pos] = src[i];
    }
}

// ---------------------------------------------------------------------------
// GEMM: C[M,BN] = A[M,128] @ W[128,BN] ; hs_out = C * dis[row]
// BM=64, 256 threads, 4 x TN micro-tile (round-2 shape).
// ---------------------------------------------------------------------------
template <int BN>
__global__ __launch_bounds__(256) void gemm_kernel(const float* __restrict__ A,
                                                   const float* __restrict__ W,
                                                   const float* __restrict__ dis,
                                                   float* __restrict__ hs_out, int M) {
    constexpr int TN = BN / 16;
    __shared__ float As[16][64];   // As[k][m]
    __shared__ float Bs[16][BN];   // Bs[k][n]

    const int tid  = threadIdx.x;
    const int tx   = tid & 15;
    const int ty   = tid >> 4;
    const int row0 = blockIdx.x * 64;

    float acc[4][TN];
#pragma unroll
    for (int i = 0; i < 4; i++)
#pragma unroll
        for (int j = 0; j < TN; j++) acc[i][j] = 0.f;

    const int lr   = tid >> 2;
    const int lk   = (tid & 3) * 4;
    const int arow = row0 + lr;

    for (int k0 = 0; k0 < 128; k0 += 16) {
        float4 av = make_float4(0.f, 0.f, 0.f, 0.f);
        if (arow < M) av = *(const float4*)(A + (size_t)arow * 128 + k0 + lk);
        As[lk + 0][lr] = av.x; As[lk + 1][lr] = av.y;
        As[lk + 2][lr] = av.z; As[lk + 3][lr] = av.w;

#pragma unroll
        for (int t = 0; t < (16 * BN) / 1024; t++) {
            int f4 = tid + t * 256;
            int kk = f4 / (BN / 4);
            int jj = (f4 % (BN / 4)) * 4;
            *(float4*)&Bs[kk][jj] = *(const float4*)(W + (size_t)(k0 + kk) * BN + jj);
        }
        __syncthreads();

#pragma unroll
        for (int k = 0; k < 16; k++) {
            float4 at = *(const float4*)&As[k][ty * 4];
            float a[4] = {at.x, at.y, at.z, at.w};
            float b[TN];
#pragma unroll
            for (int j = 0; j < TN; j += 4) {
                float4 bt = *(const float4*)&Bs[k][tx * TN + j];
                b[j] = bt.x; b[j + 1] = bt.y; b[j + 2] = bt.z; b[j + 3] = bt.w;
            }
#pragma unroll
            for (int i = 0; i < 4; i++)
#pragma unroll
                for (int j = 0; j < TN; j++)
                    acc[i][j] = fmaf(a[i], b[j], acc[i][j]);
        }
        __syncthreads();
    }

#pragma unroll
    for (int i = 0; i < 4; i++) {
        int row = row0 + ty * 4 + i;
        if (row < M) {
            float dd = __ldg(dis + row);
#pragma unroll
            for (int j = 0; j < TN; j += 4) {
                float4 o = make_float4(acc[i][j] * dd, acc[i][j + 1] * dd,
                                       acc[i][j + 2] * dd, acc[i][j + 3] * dd);
                *(float4*)(hs_out + (size_t)row * BN + tx * TN + j) = o;
            }
        }
    }
}

// ---------------------------------------------------------------------------
// Aggregation + combine (CSR segment sum, no atomics):
//   outA[d,f] = relu( dis[d] * ( hs[d,f] + sum_{s in N(d)} hs[s,f] ) + b[f] )
// One block per dst node, thread = feature, 4 accumulators for MLP.
// ---------------------------------------------------------------------------
template <int F>
__global__ __launch_bounds__(F) void agg_combine_kernel(
    const float* __restrict__ hs, const int* __restrict__ rowptr,
    const int* __restrict__ colsrc, const float* __restrict__ dis,
    const float* __restrict__ bias, float* __restrict__ outA, int n)
{
    int node = blockIdx.x;
    int f    = threadIdx.x;
    int beg  = __ldg(rowptr + node);
    int end  = __ldg(rowptr + node + 1);

    float s0 = __ldg(hs + (size_t)node * F + f);   // self-loop term
    float s1 = 0.f, s2 = 0.f, s3 = 0.f;
    int p = beg;
    for (; p + 4 <= end; p += 4) {
        int i0 = __ldg(colsrc + p + 0);
        int i1 = __ldg(colsrc + p + 1);
        int i2 = __ldg(colsrc + p + 2);
        int i3 = __ldg(colsrc + p + 3);
        s0 += __ldg(hs + (size_t)i0 * F + f);
        s1 += __ldg(hs + (size_t)i1 * F + f);
        s2 += __ldg(hs + (size_t)i2 * F + f);
        s3 += __ldg(hs + (size_t)i3 * F + f);
    }
    for (; p < end; ++p)
        s0 += __ldg(hs + (size_t)__ldg(colsrc + p) * F + f);

    float sum = (s0 + s1) + (s2 + s3);
    outA[(size_t)node * F + f] = fmaxf(fmaf(__ldg(dis + node), sum, __ldg(bias + f)), 0.f);
}

// ---------------------------------------------------------------------------
// out = log_softmax(a, axis=1) -- input already relu'd, 64 cols, warp/node
// ---------------------------------------------------------------------------
__global__ void logsoftmax_kernel(const float* __restrict__ a, float* __restrict__ out, int n) {
    int gtid = blockIdx.x * blockDim.x + threadIdx.x;
    int warp = gtid >> 5;
    int lane = gtid & 31;
    if (warp >= n) return;
    const float* row = a + (size_t)warp * 64;
    float v0 = row[lane];
    float v1 = row[lane + 32];
    float m = fmaxf(v0, v1);
#pragma unroll
    for (int off = 16; off > 0; off >>= 1)
        m = fmaxf(m, __shfl_xor_sync(0xffffffffu, m, off));
    float s = expf(v0 - m) + expf(v1 - m);
#pragma unroll
    for (int off = 16; off > 0; off >>= 1)
        s += __shfl_xor_sync(0xffffffffu, s, off);
    float ls = logf(s);
    float* orow = out + (size_t)warp * 64;
    orow[lane]      = v0 - m - ls;
    orow[lane + 32] = v1 - m - ls;
}

// ---------------------------------------------------------------------------
// Launch
// ---------------------------------------------------------------------------
extern "C" void kernel_launch(void* const* d_in, const int* in_sizes, int n_in,
                              void* d_out, int out_size) {
    const float* x  = (const float*)d_in[0];
    const int*   ei = (const int*)d_in[1];
    const float* W0 = (const float*)d_in[2];
    const float* b0 = (const float*)d_in[3];
    const float* W1 = (const float*)d_in[4];
    const float* b1 = (const float*)d_in[5];
    const float* W2 = (const float*)d_in[6];
    const float* b2 = (const float*)d_in[7];
    float* out = (float*)d_out;

    const int E = in_sizes[1] / 2;
    const int N = in_sizes[0] / DIM;
    const int* src = ei;
    const int* dst = ei + E;

    float *p_dis, *p_h, *p_a;
    int *p_cnt, *p_rowptr, *p_cursor, *p_colsrc;
    cudaGetSymbolAddress((void**)&p_dis,    g_dis);
    cudaGetSymbolAddress((void**)&p_h,      g_h);
    cudaGetSymbolAddress((void**)&p_a,      g_a);
    cudaGetSymbolAddress((void**)&p_cnt,    g_cnt);
    cudaGetSymbolAddress((void**)&p_rowptr, g_rowptr);
    cudaGetSymbolAddress((void**)&p_cursor, g_cursor);
    cudaGetSymbolAddress((void**)&p_colsrc, g_colsrc);

    const int T = 256;
    const int gemm_blocks = (N + 63) / 64;

    // Normalization + CSR build (by dst)
    init_kernel<<<(N + T - 1) / T, T>>>(p_dis, p_cnt, N);
    count_kernel<<<(E + T - 1) / T, T>>>(dst, p_dis, p_cnt, E);
    rsqrt_kernel<<<(N + T - 1) / T, T>>>(p_dis, N);
    scan_kernel<<<1, 1024>>>(p_cnt, p_rowptr, N);
    copy_cursor_kernel<<<(N + T - 1) / T, T>>>(p_rowptr, p_cursor, N);
    fill_kernel<<<(E + T - 1) / T, T>>>(src, dst, p_cursor, p_colsrc, E);

    // Layer 0: hs = (x@W0)*dis ; A = relu(dis*segsum + b0)
    gemm_kernel<128><<<gemm_blocks, 256>>>(x, W0, p_dis, p_h, N);
    agg_combine_kernel<128><<<N, 128>>>(p_h, p_rowptr, p_colsrc, p_dis, b0, p_a, N);

    // Layer 1
    gemm_kernel<128><<<gemm_blocks, 256>>>(p_a, W1, p_dis, p_h, N);
    agg_combine_kernel<128><<<N, 128>>>(p_h, p_rowptr, p_colsrc, p_dis, b1, p_a, N);

    // Layer 2 (64 cols)
    gemm_kernel<64><<<gemm_blocks, 256>>>(p_a, W2, p_dis, p_h, N);
    agg_combine_kernel<64><<<N, 64>>>(p_h, p_rowptr, p_colsrc, p_dis, b2, p_a, N);

    // log_softmax
    logsoftmax_kernel<<<(N * 32 + T - 1) / T, T>>>(p_a, out, N);
}

// round 6
// speedup vs baseline: 1.9629x; 1.2302x over previous
#include <cuda_runtime.h>
#include <math.h>

#define NN   100000
#define EE   1600000
#define DIM  128

// Scratch (static device globals: no allocations allowed)
__device__ float g_dis[NN];
__device__ float g_h [(size_t)NN * DIM];   // hs = (A@W)*dis of current layer
__device__ float g_a [(size_t)NN * DIM];   // combined activation (next layer input)
__device__ int   g_cnt[NN];                // in-degree histogram
__device__ int   g_rowptr[NN + 1];         // CSR row pointers (by dst)
__device__ int   g_cursor[NN];             // fill cursors
__device__ int   g_colsrc[EE];             // src node id per CSR slot
__device__ int   g_blocksum[1024];         // per-block partial sums for scan

// ---------------------------------------------------------------------------
// in-degree histogram (int only; float degree derived later as cnt+1)
// ---------------------------------------------------------------------------
__global__ void count_kernel(const int* __restrict__ dst, int* cnt, int e) {
    int i = blockIdx.x * blockDim.x + threadIdx.x;
    if (i < e) atomicAdd(&cnt[dst[i]], 1);
}

// ---------------------------------------------------------------------------
// Multi-block exclusive scan, phase 1: per-1024-block scan + block totals
// ---------------------------------------------------------------------------
__global__ __launch_bounds__(1024) void scan_block_kernel(const int* __restrict__ cnt,
                                                          int* __restrict__ rowptr,
                                                          int* __restrict__ blocksum, int n) {
    __shared__ int wsum[32];
    const int tid = threadIdx.x, lane = tid & 31, wid = tid >> 5;
    int i = blockIdx.x * 1024 + tid;
    int v = (i < n) ? cnt[i] : 0;
    int x = v;
#pragma unroll
    for (int off = 1; off < 32; off <<= 1) {
        int t = __shfl_up_sync(0xffffffffu, x, off);
        if (lane >= off) x += t;
    }
    if (lane == 31) wsum[wid] = x;
    __syncthreads();
    if (wid == 0) {
        int w = wsum[lane];
#pragma unroll
        for (int off = 1; off < 32; off <<= 1) {
            int t = __shfl_up_sync(0xffffffffu, w, off);
            if (lane >= off) w += t;
        }
        wsum[lane] = w;
    }
    __syncthreads();
    int excl = x - v + (wid ? wsum[wid - 1] : 0);
    if (i < n) rowptr[i] = excl;
    if (tid == 1023) blocksum[blockIdx.x] = wsum[31];
}

// phase 2: exclusive scan over block totals (tiny, nb ~ 98)
__global__ void scan_carry_kernel(int* blocksum, int nb) {
    if (threadIdx.x == 0) {
        int acc = 0;
        for (int i = 0; i < nb; i++) { int v = blocksum[i]; blocksum[i] = acc; acc += v; }
    }
}

// phase 3: add carries; also emit cursor copy and dis = rsqrt(cnt+1)
__global__ void scan_add_kernel(int* __restrict__ rowptr, const int* __restrict__ blocksum,
                                const int* __restrict__ cnt, int* __restrict__ cur,
                                float* __restrict__ dis, int n, int e) {
    int i = blockIdx.x * blockDim.x + threadIdx.x;
    if (i < n) {
        int r = rowptr[i] + blocksum[i >> 10];
        rowptr[i] = r;
        cur[i]    = r;
        dis[i]    = rsqrtf((float)cnt[i] + 1.0f);
    }
    if (i == 0) rowptr[n] = e;
}

// colsrc[slot] = src, grouped by dst
__global__ void fill_kernel(const int* __restrict__ src, const int* __restrict__ dst,
                            int* __restrict__ cur, int* __restrict__ colsrc, int e) {
    int i = blockIdx.x * blockDim.x + threadIdx.x;
    if (i < e) {
        int pos = atomicAdd(&cur[dst[i]], 1);
        colsrc[pos] = src[i];
    }
}

// ---------------------------------------------------------------------------
// GEMM (BN=128): C = A[M,128] @ W[128,128] ; hs = C * dis[row]
// BM=128, 256 threads, 8x8 micro-tile, simple sync loop (no prefetch).
// ---------------------------------------------------------------------------
__global__ __launch_bounds__(256, 2) void gemm8_kernel(const float* __restrict__ A,
                                                       const float* __restrict__ W,
                                                       const float* __restrict__ dis,
                                                       float* __restrict__ hs_out, int M) {
    __shared__ float As[16][128];
    __shared__ float Bs[16][128];

    const int tid  = threadIdx.x;
    const int tx   = tid & 15;       // col group (8 cols each)
    const int ty   = tid >> 4;       // row group (8 rows each)
    const int row0 = blockIdx.x * 128;
    const int lr   = tid >> 1;       // 0..127 : row for A load
    const int lk   = (tid & 1) * 8;  // 0 or 8 : k offset for A load
    const int arow = row0 + lr;

    float acc[8][8];
#pragma unroll
    for (int i = 0; i < 8; i++)
#pragma unroll
        for (int j = 0; j < 8; j++) acc[i][j] = 0.f;

    for (int k0 = 0; k0 < 128; k0 += 16) {
        float4 a0 = make_float4(0.f, 0.f, 0.f, 0.f);
        float4 a1 = make_float4(0.f, 0.f, 0.f, 0.f);
        if (arow < M) {
            a0 = *(const float4*)(A + (size_t)arow * 128 + k0 + lk);
            a1 = *(const float4*)(A + (size_t)arow * 128 + k0 + lk + 4);
        }
        As[lk + 0][lr] = a0.x; As[lk + 1][lr] = a0.y;
        As[lk + 2][lr] = a0.z; As[lk + 3][lr] = a0.w;
        As[lk + 4][lr] = a1.x; As[lk + 5][lr] = a1.y;
        As[lk + 6][lr] = a1.z; As[lk + 7][lr] = a1.w;

#pragma unroll
        for (int t = 0; t < 2; t++) {
            int f4 = tid + t * 256;          // float4 index in 16x128 tile
            int kk = f4 >> 5;
            int jj = (f4 & 31) * 4;
            *(float4*)&Bs[kk][jj] = *(const float4*)(W + (size_t)(k0 + kk) * 128 + jj);
        }
        __syncthreads();

#pragma unroll
        for (int k = 0; k < 16; k++) {
            float4 x0 = *(const float4*)&As[k][ty * 8];
            float4 x1 = *(const float4*)&As[k][ty * 8 + 4];
            float4 y0 = *(const float4*)&Bs[k][tx * 8];
            float4 y1 = *(const float4*)&Bs[k][tx * 8 + 4];
            float a[8] = {x0.x, x0.y, x0.z, x0.w, x1.x, x1.y, x1.z, x1.w};
            float b[8] = {y0.x, y0.y, y0.z, y0.w, y1.x, y1.y, y1.z, y1.w};
#pragma unroll
            for (int i = 0; i < 8; i++)
#pragma unroll
                for (int j = 0; j < 8; j++)
                    acc[i][j] = fmaf(a[i], b[j], acc[i][j]);
        }
        __syncthreads();
    }

#pragma unroll
    for (int i = 0; i < 8; i++) {
        int row = row0 + ty * 8 + i;
        if (row < M) {
            float dd = __ldg(dis + row);
            float4 o0 = make_float4(acc[i][0] * dd, acc[i][1] * dd, acc[i][2] * dd, acc[i][3] * dd);
            float4 o1 = make_float4(acc[i][4] * dd, acc[i][5] * dd, acc[i][6] * dd, acc[i][7] * dd);
            *(float4*)(hs_out + (size_t)row * 128 + tx * 8)     = o0;
            *(float4*)(hs_out + (size_t)row * 128 + tx * 8 + 4) = o1;
        }
    }
}

// ---------------------------------------------------------------------------
// GEMM (BN=64): proven round-2 shape (BM=64, 256 threads, 4x4 micro-tile)
// ---------------------------------------------------------------------------
__global__ __launch_bounds__(256) void gemm64_kernel(const float* __restrict__ A,
                                                     const float* __restrict__ W,
                                                     const float* __restrict__ dis,
                                                     float* __restrict__ hs_out, int M) {
    constexpr int BN = 64, TN = 4;
    __shared__ float As[16][64];
    __shared__ float Bs[16][BN];

    const int tid  = threadIdx.x;
    const int tx   = tid & 15;
    const int ty   = tid >> 4;
    const int row0 = blockIdx.x * 64;

    float acc[4][TN];
#pragma unroll
    for (int i = 0; i < 4; i++)
#pragma unroll
        for (int j = 0; j < TN; j++) acc[i][j] = 0.f;

    const int lr   = tid >> 2;
    const int lk   = (tid & 3) * 4;
    const int arow = row0 + lr;

    for (int k0 = 0; k0 < 128; k0 += 16) {
        float4 av = make_float4(0.f, 0.f, 0.f, 0.f);
        if (arow < M) av = *(const float4*)(A + (size_t)arow * 128 + k0 + lk);
        As[lk + 0][lr] = av.x; As[lk + 1][lr] = av.y;
        As[lk + 2][lr] = av.z; As[lk + 3][lr] = av.w;

        {
            int f4 = tid;                  // 16*64/4 = 256 float4
            int kk = f4 >> 4;
            int jj = (f4 & 15) * 4;
            *(float4*)&Bs[kk][jj] = *(const float4*)(W + (size_t)(k0 + kk) * BN + jj);
        }
        __syncthreads();

#pragma unroll
        for (int k = 0; k < 16; k++) {
            float4 at = *(const float4*)&As[k][ty * 4];
            float a[4] = {at.x, at.y, at.z, at.w};
            float4 bt = *(const float4*)&Bs[k][tx * TN];
            float b[TN] = {bt.x, bt.y, bt.z, bt.w};
#pragma unroll
            for (int i = 0; i < 4; i++)
#pragma unroll
                for (int j = 0; j < TN; j++)
                    acc[i][j] = fmaf(a[i], b[j], acc[i][j]);
        }
        __syncthreads();
    }

#pragma unroll
    for (int i = 0; i < 4; i++) {
        int row = row0 + ty * 4 + i;
        if (row < M) {
            float dd = __ldg(dis + row);
            float4 o = make_float4(acc[i][0] * dd, acc[i][1] * dd,
                                   acc[i][2] * dd, acc[i][3] * dd);
            *(float4*)(hs_out + (size_t)row * BN + tx * TN) = o;
        }
    }
}

// ---------------------------------------------------------------------------
// Aggregation + combine (CSR segment sum, no atomics):
//   outA[d,f] = relu( dis[d] * ( hs[d,f] + sum_{s in N(d)} hs[s,f] ) + b[f] )
// ---------------------------------------------------------------------------
template <int F>
__global__ __launch_bounds__(F) void agg_combine_kernel(
    const float* __restrict__ hs, const int* __restrict__ rowptr,
    const int* __restrict__ colsrc, const float* __restrict__ dis,
    const float* __restrict__ bias, float* __restrict__ outA, int n)
{
    int node = blockIdx.x;
    int f    = threadIdx.x;
    int beg  = __ldg(rowptr + node);
    int end  = __ldg(rowptr + node + 1);

    float s0 = __ldg(hs + (size_t)node * F + f);   // self-loop term
    float s1 = 0.f, s2 = 0.f, s3 = 0.f;
    int p = beg;
    for (; p + 4 <= end; p += 4) {
        int i0 = __ldg(colsrc + p + 0);
        int i1 = __ldg(colsrc + p + 1);
        int i2 = __ldg(colsrc + p + 2);
        int i3 = __ldg(colsrc + p + 3);
        s0 += __ldg(hs + (size_t)i0 * F + f);
        s1 += __ldg(hs + (size_t)i1 * F + f);
        s2 += __ldg(hs + (size_t)i2 * F + f);
        s3 += __ldg(hs + (size_t)i3 * F + f);
    }
    for (; p < end; ++p)
        s0 += __ldg(hs + (size_t)__ldg(colsrc + p) * F + f);

    float sum = (s0 + s1) + (s2 + s3);
    outA[(size_t)node * F + f] = fmaxf(fmaf(__ldg(dis + node), sum, __ldg(bias + f)), 0.f);
}

// ---------------------------------------------------------------------------
// out = log_softmax(a, axis=1) -- input already relu'd, 64 cols, warp/node
// ---------------------------------------------------------------------------
__global__ void logsoftmax_kernel(const float* __restrict__ a, float* __restrict__ out, int n) {
    int gtid = blockIdx.x * blockDim.x + threadIdx.x;
    int warp = gtid >> 5;
    int lane = gtid & 31;
    if (warp >= n) return;
    const float* row = a + (size_t)warp * 64;
    float v0 = row[lane];
    float v1 = row[lane + 32];
    float m = fmaxf(v0, v1);
#pragma unroll
    for (int off = 16; off > 0; off >>= 1)
        m = fmaxf(m, __shfl_xor_sync(0xffffffffu, m, off));
    float s = expf(v0 - m) + expf(v1 - m);
#pragma unroll
    for (int off = 16; off > 0; off >>= 1)
        s += __shfl_xor_sync(0xffffffffu, s, off);
    float ls = logf(s);
    float* orow = out + (size_t)warp * 64;
    orow[lane]      = v0 - m - ls;
    orow[lane + 32] = v1 - m - ls;
}

// ---------------------------------------------------------------------------
// Launch
// ---------------------------------------------------------------------------
extern "C" void kernel_launch(void* const* d_in, const int* in_sizes, int n_in,
                              void* d_out, int out_size) {
    const float* x  = (const float*)d_in[0];
    const int*   ei = (const int*)d_in[1];
    const float* W0 = (const float*)d_in[2];
    const float* b0 = (const float*)d_in[3];
    const float* W1 = (const float*)d_in[4];
    const float* b1 = (const float*)d_in[5];
    const float* W2 = (const float*)d_in[6];
    const float* b2 = (const float*)d_in[7];
    float* out = (float*)d_out;

    const int E = in_sizes[1] / 2;
    const int N = in_sizes[0] / DIM;
    const int* src = ei;
    const int* dst = ei + E;

    float *p_dis, *p_h, *p_a;
    int *p_cnt, *p_rowptr, *p_cursor, *p_colsrc, *p_blocksum;
    cudaGetSymbolAddress((void**)&p_dis,      g_dis);
    cudaGetSymbolAddress((void**)&p_h,        g_h);
    cudaGetSymbolAddress((void**)&p_a,        g_a);
    cudaGetSymbolAddress((void**)&p_cnt,      g_cnt);
    cudaGetSymbolAddress((void**)&p_rowptr,   g_rowptr);
    cudaGetSymbolAddress((void**)&p_cursor,   g_cursor);
    cudaGetSymbolAddress((void**)&p_colsrc,   g_colsrc);
    cudaGetSymbolAddress((void**)&p_blocksum, g_blocksum);

    const int T = 256;
    const int nb = (N + 1023) / 1024;

    // CSR build (by dst) + normalization
    cudaMemsetAsync(p_cnt, 0, (size_t)N * sizeof(int));
    count_kernel<<<(E + T - 1) / T, T>>>(dst, p_cnt, E);
    scan_block_kernel<<<nb, 1024>>>(p_cnt, p_rowptr, p_blocksum, N);
    scan_carry_kernel<<<1, 32>>>(p_blocksum, nb);
    scan_add_kernel<<<(N + T - 1) / T, T>>>(p_rowptr, p_blocksum, p_cnt, p_cursor, p_dis, N, E);
    fill_kernel<<<(E + T - 1) / T, T>>>(src, dst, p_cursor, p_colsrc, E);

    // Layer 0: hs = (x@W0)*dis ; A = relu(dis*segsum + b0)
    gemm8_kernel<<<(N + 127) / 128, 256>>>(x, W0, p_dis, p_h, N);
    agg_combine_kernel<128><<<N, 128>>>(p_h, p_rowptr, p_colsrc, p_dis, b0, p_a, N);

    // Layer 1
    gemm8_kernel<<<(N + 127) / 128, 256>>>(p_a, W1, p_dis, p_h, N);
    agg_combine_kernel<128><<<N, 128>>>(p_h, p_rowptr, p_colsrc, p_dis, b1, p_a, N);

    // Layer 2 (64 cols)
    gemm64_kernel<<<(N + 63) / 64, 256>>>(p_a, W2, p_dis, p_h, N);
    agg_combine_kernel<64><<<N, 64>>>(p_h, p_rowptr, p_colsrc, p_dis, b2, p_a, N);

    // log_softmax
    logsoftmax_kernel<<<(N * 32 + T - 1) / T, T>>>(p_a, out, N);
}

// round 7
// speedup vs baseline: 2.1776x; 1.1094x over previous
#include <cuda_runtime.h>
#include <cuda_bf16.h>
#include <mma.h>
#include <math.h>

using namespace nvcuda;

#define NN   100000
#define EE   1600000
#define DIM  128

// Scratch (static device globals: no allocations allowed)
__device__ float g_dis[NN];
__device__ float g_h [(size_t)NN * DIM];   // hs = (A@W)*dis of current layer
__device__ float g_a [(size_t)NN * DIM];   // combined activation (next layer input)
__device__ int   g_cnt[NN];                // in-degree histogram
__device__ int   g_rowptr[NN + 1];         // CSR row pointers (by dst)
__device__ int   g_cursor[NN];             // fill cursors
__device__ int   g_colsrc[EE];             // src node id per CSR slot
__device__ int   g_blocksum[1024];         // per-block partial sums for scan
// Split weights (bf16 hi/lo)
__device__ __nv_bfloat16 g_W0h[16384], g_W0l[16384];
__device__ __nv_bfloat16 g_W1h[16384], g_W1l[16384];
__device__ __nv_bfloat16 g_W2h[8192],  g_W2l[8192];

__device__ __forceinline__ void split_bf16(float v, __nv_bfloat16& h, __nv_bfloat16& l) {
    h = __float2bfloat16(v);
    l = __float2bfloat16(v - __bfloat162float(h));
}

// ---------------------------------------------------------------------------
// Weight split: W(fp32) -> Wh + Wl (bf16)
// ---------------------------------------------------------------------------
__global__ void split_w_kernel(const float* __restrict__ W, __nv_bfloat16* __restrict__ Wh,
                               __nv_bfloat16* __restrict__ Wl, int n) {
    int i = blockIdx.x * blockDim.x + threadIdx.x;
    if (i < n) {
        __nv_bfloat16 h, l;
        split_bf16(W[i], h, l);
        Wh[i] = h; Wl[i] = l;
    }
}

// ---------------------------------------------------------------------------
// in-degree histogram
// ---------------------------------------------------------------------------
__global__ void count_kernel(const int* __restrict__ dst, int* cnt, int e) {
    int i = blockIdx.x * blockDim.x + threadIdx.x;
    if (i < e) atomicAdd(&cnt[dst[i]], 1);
}

// ---------------------------------------------------------------------------
// Multi-block exclusive scan, phase 1
// ---------------------------------------------------------------------------
__global__ __launch_bounds__(1024) void scan_block_kernel(const int* __restrict__ cnt,
                                                          int* __restrict__ rowptr,
                                                          int* __restrict__ blocksum, int n) {
    __shared__ int wsum[32];
    const int tid = threadIdx.x, lane = tid & 31, wid = tid >> 5;
    int i = blockIdx.x * 1024 + tid;
    int v = (i < n) ? cnt[i] : 0;
    int x = v;
#pragma unroll
    for (int off = 1; off < 32; off <<= 1) {
        int t = __shfl_up_sync(0xffffffffu, x, off);
        if (lane >= off) x += t;
    }
    if (lane == 31) wsum[wid] = x;
    __syncthreads();
    if (wid == 0) {
        int w = wsum[lane];
#pragma unroll
        for (int off = 1; off < 32; off <<= 1) {
            int t = __shfl_up_sync(0xffffffffu, w, off);
            if (lane >= off) w += t;
        }
        wsum[lane] = w;
    }
    __syncthreads();
    int excl = x - v + (wid ? wsum[wid - 1] : 0);
    if (i < n) rowptr[i] = excl;
    if (tid == 1023) blocksum[blockIdx.x] = wsum[31];
}

__global__ void scan_carry_kernel(int* blocksum, int nb) {
    if (threadIdx.x == 0) {
        int acc = 0;
        for (int i = 0; i < nb; i++) { int v = blocksum[i]; blocksum[i] = acc; acc += v; }
    }
}

__global__ void scan_add_kernel(int* __restrict__ rowptr, const int* __restrict__ blocksum,
                                const int* __restrict__ cnt, int* __restrict__ cur,
                                float* __restrict__ dis, int n, int e) {
    int i = blockIdx.x * blockDim.x + threadIdx.x;
    if (i < n) {
        int r = rowptr[i] + blocksum[i >> 10];
        rowptr[i] = r;
        cur[i]    = r;
        dis[i]    = rsqrtf((float)cnt[i] + 1.0f);
    }
    if (i == 0) rowptr[n] = e;
}

__global__ void fill_kernel(const int* __restrict__ src, const int* __restrict__ dst,
                            int* __restrict__ cur, int* __restrict__ colsrc, int e) {
    int i = blockIdx.x * blockDim.x + threadIdx.x;
    if (i < e) {
        int pos = atomicAdd(&cur[dst[i]], 1);
        colsrc[pos] = src[i];
    }
}

// ---------------------------------------------------------------------------
// Tensor-core GEMM (bf16 split, fp32-equivalent accuracy):
//   C = A[M,128] @ W[128,BN] ; hs = C * dis[row]
// BM=64, 256 threads = 8 warps (4 along M x 2 along N), warp tile 16 x BN/2.
// Per k-stage (BK=16): A tile split to bf16 hi/lo in smem; W hi/lo pre-split.
// acc += Ah*Bh + Ah*Bl + Al*Bh.
// ---------------------------------------------------------------------------
template <int BN>
__global__ __launch_bounds__(256) void gemm_tc_kernel(
    const float* __restrict__ A,
    const __nv_bfloat16* __restrict__ Bh_g,
    const __nv_bfloat16* __restrict__ Bl_g,
    const float* __restrict__ dis,
    float* __restrict__ hs_out, int M)
{
    constexpr int WN  = BN / 2;       // warp n-extent
    constexpr int FN  = WN / 16;      // fragments per warp along n
    constexpr int LDA = 24;           // padded smem ld for A (elements)
    constexpr int LDB = BN + 8;       // padded smem ld for B (elements)

    __shared__ __align__(16) unsigned char smem_raw[64 * BN * 4];  // epilogue C dominates

    __nv_bfloat16* Ah  = (__nv_bfloat16*)smem_raw;       // 64*LDA
    __nv_bfloat16* Al  = Ah  + 64 * LDA;
    __nv_bfloat16* Bsh = Al  + 64 * LDA;                 // 16*LDB
    __nv_bfloat16* Bsl = Bsh + 16 * LDB;

    const int tid  = threadIdx.x;
    const int wid  = tid >> 5;
    const int wm   = wid & 3;          // warp row (x16)
    const int wn   = wid >> 2;         // warp col (x WN)
    const int row0 = blockIdx.x * 64;

    wmma::fragment<wmma::accumulator, 16, 16, 16, float> acc[FN];
#pragma unroll
    for (int j = 0; j < FN; j++) wmma::fill_fragment(acc[j], 0.f);

    // A-load mapping: 4 threads per row (16 floats), 64 rows
    const int ar = tid >> 2;
    const int ak = (tid & 3) * 4;
    const int arow = row0 + ar;

    for (int s = 0; s < 8; s++) {
        // --- stage A tile (64 x 16 fp32 -> bf16 hi/lo) ---
        float4 v = make_float4(0.f, 0.f, 0.f, 0.f);
        if (arow < M) v = *(const float4*)(A + (size_t)arow * 128 + s * 16 + ak);
        {
            __nv_bfloat16 h, l;
            split_bf16(v.x, h, l); Ah[ar * LDA + ak + 0] = h; Al[ar * LDA + ak + 0] = l;
            split_bf16(v.y, h, l); Ah[ar * LDA + ak + 1] = h; Al[ar * LDA + ak + 1] = l;
            split_bf16(v.z, h, l); Ah[ar * LDA + ak + 2] = h; Al[ar * LDA + ak + 2] = l;
            split_bf16(v.w, h, l); Ah[ar * LDA + ak + 3] = h; Al[ar * LDA + ak + 3] = l;
        }
        // --- stage B tile (16 x BN bf16 hi/lo), vectorized 16B ---
        if (BN == 128) {
            int r = tid >> 4, c = (tid & 15) * 8;          // 16 thr/row
            *(uint4*)&Bsh[r * LDB + c] = *(const uint4*)&Bh_g[(size_t)(s * 16 + r) * BN + c];
            *(uint4*)&Bsl[r * LDB + c] = *(const uint4*)&Bl_g[(size_t)(s * 16 + r) * BN + c];
        } else {
            if (tid < 128) {
                int r = tid >> 3, c = (tid & 7) * 8;       // 8 thr/row
                *(uint4*)&Bsh[r * LDB + c] = *(const uint4*)&Bh_g[(size_t)(s * 16 + r) * BN + c];
                *(uint4*)&Bsl[r * LDB + c] = *(const uint4*)&Bl_g[(size_t)(s * 16 + r) * BN + c];
            }
        }
        __syncthreads();

        // --- MMA ---
        wmma::fragment<wmma::matrix_a, 16, 16, 16, __nv_bfloat16, wmma::row_major> fa_h, fa_l;
        wmma::load_matrix_sync(fa_h, Ah + wm * 16 * LDA, LDA);
        wmma::load_matrix_sync(fa_l, Al + wm * 16 * LDA, LDA);
#pragma unroll
        for (int j = 0; j < FN; j++) {
            wmma::fragment<wmma::matrix_b, 16, 16, 16, __nv_bfloat16, wmma::row_major> fb_h, fb_l;
            wmma::load_matrix_sync(fb_h, Bsh + wn * WN + j * 16, LDB);
            wmma::load_matrix_sync(fb_l, Bsl + wn * WN + j * 16, LDB);
            wmma::mma_sync(acc[j], fa_h, fb_h, acc[j]);
            wmma::mma_sync(acc[j], fa_h, fb_l, acc[j]);
            wmma::mma_sync(acc[j], fa_l, fb_h, acc[j]);
        }
        __syncthreads();
    }

    // --- epilogue: stage C in smem, scaled write ---
    float* Cs = (float*)smem_raw;
#pragma unroll
    for (int j = 0; j < FN; j++)
        wmma::store_matrix_sync(Cs + (wm * 16) * BN + wn * WN + j * 16, acc[j], BN,
                                wmma::mem_row_major);
    __syncthreads();

    constexpr int QB = BN / 4;
    for (int i = tid; i < 64 * QB; i += 256) {
        int r = i / QB, c = (i % QB) * 4;
        int row = row0 + r;
        if (row < M) {
            float dd = __ldg(dis + row);
            float4 o = *(float4*)&Cs[r * BN + c];
            o.x *= dd; o.y *= dd; o.z *= dd; o.w *= dd;
            *(float4*)(hs_out + (size_t)row * BN + c) = o;
        }
    }
}

// ---------------------------------------------------------------------------
// Aggregation + combine (CSR segment sum, no atomics):
//   outA[d,f] = relu( dis[d] * ( hs[d,f] + sum_{s in N(d)} hs[s,f] ) + b[f] )
// ---------------------------------------------------------------------------
template <int F>
__global__ __launch_bounds__(F) void agg_combine_kernel(
    const float* __restrict__ hs, const int* __restrict__ rowptr,
    const int* __restrict__ colsrc, const float* __restrict__ dis,
    const float* __restrict__ bias, float* __restrict__ outA, int n)
{
    int node = blockIdx.x;
    int f    = threadIdx.x;
    int beg  = __ldg(rowptr + node);
    int end  = __ldg(rowptr + node + 1);

    float s0 = __ldg(hs + (size_t)node * F + f);   // self-loop term
    float s1 = 0.f, s2 = 0.f, s3 = 0.f;
    int p = beg;
    for (; p + 4 <= end; p += 4) {
        int i0 = __ldg(colsrc + p + 0);
        int i1 = __ldg(colsrc + p + 1);
        int i2 = __ldg(colsrc + p + 2);
        int i3 = __ldg(colsrc + p + 3);
        s0 += __ldg(hs + (size_t)i0 * F + f);
        s1 += __ldg(hs + (size_t)i1 * F + f);
        s2 += __ldg(hs + (size_t)i2 * F + f);
        s3 += __ldg(hs + (size_t)i3 * F + f);
    }
    for (; p < end; ++p)
        s0 += __ldg(hs + (size_t)__ldg(colsrc + p) * F + f);

    float sum = (s0 + s1) + (s2 + s3);
    outA[(size_t)node * F + f] = fmaxf(fmaf(__ldg(dis + node), sum, __ldg(bias + f)), 0.f);
}

// ---------------------------------------------------------------------------
// out = log_softmax(a, axis=1) -- input already relu'd, 64 cols, warp/node
// ---------------------------------------------------------------------------
__global__ void logsoftmax_kernel(const float* __restrict__ a, float* __restrict__ out, int n) {
    int gtid = blockIdx.x * blockDim.x + threadIdx.x;
    int warp = gtid >> 5;
    int lane = gtid & 31;
    if (warp >= n) return;
    const float* row = a + (size_t)warp * 64;
    float v0 = row[lane];
    float v1 = row[lane + 32];
    float m = fmaxf(v0, v1);
#pragma unroll
    for (int off = 16; off > 0; off >>= 1)
        m = fmaxf(m, __shfl_xor_sync(0xffffffffu, m, off));
    float s = expf(v0 - m) + expf(v1 - m);
#pragma unroll
    for (int off = 16; off > 0; off >>= 1)
        s += __shfl_xor_sync(0xffffffffu, s, off);
    float ls = logf(s);
    float* orow = out + (size_t)warp * 64;
    orow[lane]      = v0 - m - ls;
    orow[lane + 32] = v1 - m - ls;
}

// ---------------------------------------------------------------------------
// Launch
// ---------------------------------------------------------------------------
extern "C" void kernel_launch(void* const* d_in, const int* in_sizes, int n_in,
                              void* d_out, int out_size) {
    const float* x  = (const float*)d_in[0];
    const int*   ei = (const int*)d_in[1];
    const float* W0 = (const float*)d_in[2];
    const float* b0 = (const float*)d_in[3];
    const float* W1 = (const float*)d_in[4];
    const float* b1 = (const float*)d_in[5];
    const float* W2 = (const float*)d_in[6];
    const float* b2 = (const float*)d_in[7];
    float* out = (float*)d_out;

    const int E = in_sizes[1] / 2;
    const int N = in_sizes[0] / DIM;
    const int* src = ei;
    const int* dst = ei + E;

    float *p_dis, *p_h, *p_a;
    int *p_cnt, *p_rowptr, *p_cursor, *p_colsrc, *p_blocksum;
    __nv_bfloat16 *p_W0h, *p_W0l, *p_W1h, *p_W1l, *p_W2h, *p_W2l;
    cudaGetSymbolAddress((void**)&p_dis,      g_dis);
    cudaGetSymbolAddress((void**)&p_h,        g_h);
    cudaGetSymbolAddress((void**)&p_a,        g_a);
    cudaGetSymbolAddress((void**)&p_cnt,      g_cnt);
    cudaGetSymbolAddress((void**)&p_rowptr,   g_rowptr);
    cudaGetSymbolAddress((void**)&p_cursor,   g_cursor);
    cudaGetSymbolAddress((void**)&p_colsrc,   g_colsrc);
    cudaGetSymbolAddress((void**)&p_blocksum, g_blocksum);
    cudaGetSymbolAddress((void**)&p_W0h, g_W0h); cudaGetSymbolAddress((void**)&p_W0l, g_W0l);
    cudaGetSymbolAddress((void**)&p_W1h, g_W1h); cudaGetSymbolAddress((void**)&p_W1l, g_W1l);
    cudaGetSymbolAddress((void**)&p_W2h, g_W2h); cudaGetSymbolAddress((void**)&p_W2l, g_W2l);

    const int T = 256;
    const int nb = (N + 1023) / 1024;
    const int gemm_blocks = (N + 63) / 64;

    // Weight splits (independent of CSR build)
    split_w_kernel<<<64, 256>>>(W0, p_W0h, p_W0l, 16384);
    split_w_kernel<<<64, 256>>>(W1, p_W1h, p_W1l, 16384);
    split_w_kernel<<<32, 256>>>(W2, p_W2h, p_W2l, 8192);

    // CSR build (by dst) + normalization
    cudaMemsetAsync(p_cnt, 0, (size_t)N * sizeof(int));
    count_kernel<<<(E + T - 1) / T, T>>>(dst, p_cnt, E);
    scan_block_kernel<<<nb, 1024>>>(p_cnt, p_rowptr, p_blocksum, N);
    scan_carry_kernel<<<1, 32>>>(p_blocksum, nb);
    scan_add_kernel<<<(N + T - 1) / T, T>>>(p_rowptr, p_blocksum, p_cnt, p_cursor, p_dis, N, E);
    fill_kernel<<<(E + T - 1) / T, T>>>(src, dst, p_cursor, p_colsrc, E);

    // Layer 0: hs = (x@W0)*dis ; A = relu(dis*segsum + b0)
    gemm_tc_kernel<128><<<gemm_blocks, 256>>>(x, p_W0h, p_W0l, p_dis, p_h, N);
    agg_combine_kernel<128><<<N, 128>>>(p_h, p_rowptr, p_colsrc, p_dis, b0, p_a, N);

    // Layer 1
    gemm_tc_kernel<128><<<gemm_blocks, 256>>>(p_a, p_W1h, p_W1l, p_dis, p_h, N);
    agg_combine_kernel<128><<<N, 128>>>(p_h, p_rowptr, p_colsrc, p_dis, b1, p_a, N);

    // Layer 2 (64 cols)
    gemm_tc_kernel<64><<<gemm_blocks, 256>>>(p_a, p_W2h, p_W2l, p_dis, p_h, N);
    agg_combine_kernel<64><<<N, 64>>>(p_h, p_rowptr, p_colsrc, p_dis, b2, p_a, N);

    // log_softmax
    logsoftmax_kernel<<<(N * 32 + T - 1) / T, T>>>(p_a, out, N);
}

// round 8
// speedup vs baseline: 2.1882x; 1.0048x over previous
#include <cuda_runtime.h>
#include <cuda_bf16.h>
#include <mma.h>
#include <math.h>

using namespace nvcuda;

#define NN   100000
#define EE   1600000
#define DIM  128

// Scratch (static device globals: no allocations allowed)
__device__ float g_dis[NN];
__device__ float g_h [(size_t)NN * DIM];   // hs = (A@W)*dis of current layer
__device__ float g_a [(size_t)NN * DIM];   // combined activation (next layer input)
__device__ int   g_cnt[NN];                // in-degree histogram
__device__ int   g_rowptr[NN + 1];         // CSR row pointers (by dst)
__device__ int   g_cursor[NN];             // fill cursors
__device__ int   g_colsrc[EE];             // src node id per CSR slot
__device__ int   g_blocksum[1024];         // per-block partial sums for scan
// Split weights (bf16 hi/lo)
__device__ __nv_bfloat16 g_W0h[16384], g_W0l[16384];
__device__ __nv_bfloat16 g_W1h[16384], g_W1l[16384];
__device__ __nv_bfloat16 g_W2h[8192],  g_W2l[8192];

__device__ __forceinline__ void split_bf16(float v, __nv_bfloat16& h, __nv_bfloat16& l) {
    h = __float2bfloat16(v);
    l = __float2bfloat16(v - __bfloat162float(h));
}

// ---------------------------------------------------------------------------
// Weight split: W(fp32) -> Wh + Wl (bf16)
// ---------------------------------------------------------------------------
__global__ void split_w_kernel(const float* __restrict__ W, __nv_bfloat16* __restrict__ Wh,
                               __nv_bfloat16* __restrict__ Wl, int n) {
    int i = blockIdx.x * blockDim.x + threadIdx.x;
    if (i < n) {
        __nv_bfloat16 h, l;
        split_bf16(W[i], h, l);
        Wh[i] = h; Wl[i] = l;
    }
}

// ---------------------------------------------------------------------------
// in-degree histogram
// ---------------------------------------------------------------------------
__global__ void count_kernel(const int* __restrict__ dst, int* cnt, int e) {
    int i = blockIdx.x * blockDim.x + threadIdx.x;
    if (i < e) atomicAdd(&cnt[dst[i]], 1);
}

// ---------------------------------------------------------------------------
// Multi-block exclusive scan, phase 1
// ---------------------------------------------------------------------------
__global__ __launch_bounds__(1024) void scan_block_kernel(const int* __restrict__ cnt,
                                                          int* __restrict__ rowptr,
                                                          int* __restrict__ blocksum, int n) {
    __shared__ int wsum[32];
    const int tid = threadIdx.x, lane = tid & 31, wid = tid >> 5;
    int i = blockIdx.x * 1024 + tid;
    int v = (i < n) ? cnt[i] : 0;
    int x = v;
#pragma unroll
    for (int off = 1; off < 32; off <<= 1) {
        int t = __shfl_up_sync(0xffffffffu, x, off);
        if (lane >= off) x += t;
    }
    if (lane == 31) wsum[wid] = x;
    __syncthreads();
    if (wid == 0) {
        int w = wsum[lane];
#pragma unroll
        for (int off = 1; off < 32; off <<= 1) {
            int t = __shfl_up_sync(0xffffffffu, w, off);
            if (lane >= off) w += t;
        }
        wsum[lane] = w;
    }
    __syncthreads();
    int excl = x - v + (wid ? wsum[wid - 1] : 0);
    if (i < n) rowptr[i] = excl;
    if (tid == 1023) blocksum[blockIdx.x] = wsum[31];
}

__global__ void scan_carry_kernel(int* blocksum, int nb) {
    if (threadIdx.x == 0) {
        int acc = 0;
        for (int i = 0; i < nb; i++) { int v = blocksum[i]; blocksum[i] = acc; acc += v; }
    }
}

__global__ void scan_add_kernel(int* __restrict__ rowptr, const int* __restrict__ blocksum,
                                const int* __restrict__ cnt, int* __restrict__ cur,
                                float* __restrict__ dis, int n, int e) {
    int i = blockIdx.x * blockDim.x + threadIdx.x;
    if (i < n) {
        int r = rowptr[i] + blocksum[i >> 10];
        rowptr[i] = r;
        cur[i]    = r;
        dis[i]    = rsqrtf((float)cnt[i] + 1.0f);
    }
    if (i == 0) rowptr[n] = e;
}

__global__ void fill_kernel(const int* __restrict__ src, const int* __restrict__ dst,
                            int* __restrict__ cur, int* __restrict__ colsrc, int e) {
    int i = blockIdx.x * blockDim.x + threadIdx.x;
    if (i < e) {
        int pos = atomicAdd(&cur[dst[i]], 1);
        colsrc[pos] = src[i];
    }
}

// ---------------------------------------------------------------------------
// Tensor-core GEMM v2 (bf16 split, fp32-equivalent accuracy):
//   C = A[M,128] @ W[128,BN] ; hs = C * dis[row]
// BM=128, 256 threads = 8 warps (4m x 2n), warp tile 32 x (BN/2).
// Full W (hi+lo) staged in smem ONCE; A split to bf16 per 16-k stage,
// double-buffered, one sync per stage.
// ---------------------------------------------------------------------------
template <int BN>
__global__ __launch_bounds__(256, 2) void gemm_tc_kernel(
    const float* __restrict__ A,
    const __nv_bfloat16* __restrict__ Bh_g,
    const __nv_bfloat16* __restrict__ Bl_g,
    const float* __restrict__ dis,
    float* __restrict__ hs_out, int M)
{
    constexpr int WN  = BN / 2;       // warp n-extent
    constexpr int FN  = WN / 16;      // n fragments per warp (4 or 2)
    constexpr int LDA = 24;           // padded A smem ld (bf16 elems)
    constexpr int LDB = BN + 8;       // padded B smem ld (bf16 elems)
    constexpr int ASZ = 128 * LDA;    // one A buffer (elems)

    extern __shared__ __align__(16) unsigned char smem_raw[];
    __nv_bfloat16* Ab = (__nv_bfloat16*)smem_raw;        // 4 buffers: h0,l0,h1,l1
    __nv_bfloat16* Bh = Ab + 4 * ASZ;                    // 128 x LDB
    __nv_bfloat16* Bl = Bh + 128 * LDB;

    const int tid  = threadIdx.x;
    const int wid  = tid >> 5;
    const int wm   = wid & 3;          // warp row (x32)
    const int wn   = wid >> 2;         // warp col (x WN)
    const int row0 = blockIdx.x * 128;

    // --- stage full W hi/lo into smem (once) ---
    constexpr int ELEMS = 128 * BN;
    for (int e = tid * 8; e < ELEMS; e += 256 * 8) {
        int r = e / BN, c = e % BN;
        *(uint4*)&Bh[r * LDB + c] = *(const uint4*)&Bh_g[e];
        *(uint4*)&Bl[r * LDB + c] = *(const uint4*)&Bl_g[e];
    }

    wmma::fragment<wmma::accumulator, 16, 16, 16, float> acc[2][FN];
#pragma unroll
    for (int i = 0; i < 2; i++)
#pragma unroll
        for (int j = 0; j < FN; j++) wmma::fill_fragment(acc[i][j], 0.f);

    // A-load mapping: 2 threads per row, 8 k each
    const int ar   = tid >> 1;         // 0..127
    const int ak   = (tid & 1) * 8;    // 0 or 8
    const int arow = row0 + ar;

    float4 v0 = make_float4(0.f, 0.f, 0.f, 0.f), v1 = v0;
    if (arow < M) {
        v0 = *(const float4*)(A + (size_t)arow * 128 + ak);
        v1 = *(const float4*)(A + (size_t)arow * 128 + ak + 4);
    }

    for (int s = 0; s < 8; s++) {
        __nv_bfloat16* pAh = Ab + (s & 1) * 2 * ASZ;
        __nv_bfloat16* pAl = pAh + ASZ;
        {
            __nv_bfloat16 h, l;
            split_bf16(v0.x, h, l); pAh[ar * LDA + ak + 0] = h; pAl[ar * LDA + ak + 0] = l;
            split_bf16(v0.y, h, l); pAh[ar * LDA + ak + 1] = h; pAl[ar * LDA + ak + 1] = l;
            split_bf16(v0.z, h, l); pAh[ar * LDA + ak + 2] = h; pAl[ar * LDA + ak + 2] = l;
            split_bf16(v0.w, h, l); pAh[ar * LDA + ak + 3] = h; pAl[ar * LDA + ak + 3] = l;
            split_bf16(v1.x, h, l); pAh[ar * LDA + ak + 4] = h; pAl[ar * LDA + ak + 4] = l;
            split_bf16(v1.y, h, l); pAh[ar * LDA + ak + 5] = h; pAl[ar * LDA + ak + 5] = l;
            split_bf16(v1.z, h, l); pAh[ar * LDA + ak + 6] = h; pAl[ar * LDA + ak + 6] = l;
            split_bf16(v1.w, h, l); pAh[ar * LDA + ak + 7] = h; pAl[ar * LDA + ak + 7] = l;
        }
        __syncthreads();

        if (s < 7 && arow < M) {
            v0 = *(const float4*)(A + (size_t)arow * 128 + (s + 1) * 16 + ak);
            v1 = *(const float4*)(A + (size_t)arow * 128 + (s + 1) * 16 + ak + 4);
        }

        wmma::fragment<wmma::matrix_a, 16, 16, 16, __nv_bfloat16, wmma::row_major> fa_h[2], fa_l[2];
#pragma unroll
        for (int i = 0; i < 2; i++) {
            wmma::load_matrix_sync(fa_h[i], pAh + (wm * 32 + i * 16) * LDA, LDA);
            wmma::load_matrix_sync(fa_l[i], pAl + (wm * 32 + i * 16) * LDA, LDA);
        }
#pragma unroll
        for (int j = 0; j < FN; j++) {
            wmma::fragment<wmma::matrix_b, 16, 16, 16, __nv_bfloat16, wmma::row_major> fb_h, fb_l;
            wmma::load_matrix_sync(fb_h, Bh + (s * 16) * LDB + wn * WN + j * 16, LDB);
            wmma::load_matrix_sync(fb_l, Bl + (s * 16) * LDB + wn * WN + j * 16, LDB);
#pragma unroll
            for (int i = 0; i < 2; i++) {
                wmma::mma_sync(acc[i][j], fa_h[i], fb_h, acc[i][j]);
                wmma::mma_sync(acc[i][j], fa_h[i], fb_l, acc[i][j]);
                wmma::mma_sync(acc[i][j], fa_l[i], fb_h, acc[i][j]);
            }
        }
    }

    // --- epilogue: stage C in smem (reuses A/B region), scaled write ---
    __syncthreads();
    float* Cs = (float*)smem_raw;
#pragma unroll
    for (int i = 0; i < 2; i++)
#pragma unroll
        for (int j = 0; j < FN; j++)
            wmma::store_matrix_sync(Cs + (wm * 32 + i * 16) * BN + wn * WN + j * 16,
                                    acc[i][j], BN, wmma::mem_row_major);
    __syncthreads();

    constexpr int QB = BN / 4;
    for (int i = tid; i < 128 * QB; i += 256) {
        int r = i / QB, c = (i % QB) * 4;
        int row = row0 + r;
        if (row < M) {
            float dd = __ldg(dis + row);
            float4 o = *(float4*)&Cs[r * BN + c];
            o.x *= dd; o.y *= dd; o.z *= dd; o.w *= dd;
            *(float4*)(hs_out + (size_t)row * BN + c) = o;
        }
    }
}

// ---------------------------------------------------------------------------
// Aggregation + combine (CSR segment sum, no atomics):
//   outA[d,f] = relu( dis[d] * ( hs[d,f] + sum_{s in N(d)} hs[s,f] ) + b[f] )
// ---------------------------------------------------------------------------
template <int F>
__global__ __launch_bounds__(F) void agg_combine_kernel(
    const float* __restrict__ hs, const int* __restrict__ rowptr,
    const int* __restrict__ colsrc, const float* __restrict__ dis,
    const float* __restrict__ bias, float* __restrict__ outA, int n)
{
    int node = blockIdx.x;
    int f    = threadIdx.x;
    int beg  = __ldg(rowptr + node);
    int end  = __ldg(rowptr + node + 1);

    float s0 = __ldg(hs + (size_t)node * F + f);   // self-loop term
    float s1 = 0.f, s2 = 0.f, s3 = 0.f;
    int p = beg;
    for (; p + 4 <= end; p += 4) {
        int i0 = __ldg(colsrc + p + 0);
        int i1 = __ldg(colsrc + p + 1);
        int i2 = __ldg(colsrc + p + 2);
        int i3 = __ldg(colsrc + p + 3);
        s0 += __ldg(hs + (size_t)i0 * F + f);
        s1 += __ldg(hs + (size_t)i1 * F + f);
        s2 += __ldg(hs + (size_t)i2 * F + f);
        s3 += __ldg(hs + (size_t)i3 * F + f);
    }
    for (; p < end; ++p)
        s0 += __ldg(hs + (size_t)__ldg(colsrc + p) * F + f);

    float sum = (s0 + s1) + (s2 + s3);
    outA[(size_t)node * F + f] = fmaxf(fmaf(__ldg(dis + node), sum, __ldg(bias + f)), 0.f);
}

// ---------------------------------------------------------------------------
// out = log_softmax(a, axis=1) -- input already relu'd, 64 cols, warp/node
// ---------------------------------------------------------------------------
__global__ void logsoftmax_kernel(const float* __restrict__ a, float* __restrict__ out, int n) {
    int gtid = blockIdx.x * blockDim.x + threadIdx.x;
    int warp = gtid >> 5;
    int lane = gtid & 31;
    if (warp >= n) return;
    const float* row = a + (size_t)warp * 64;
    float v0 = row[lane];
    float v1 = row[lane + 32];
    float m = fmaxf(v0, v1);
#pragma unroll
    for (int off = 16; off > 0; off >>= 1)
        m = fmaxf(m, __shfl_xor_sync(0xffffffffu, m, off));
    float s = expf(v0 - m) + expf(v1 - m);
#pragma unroll
    for (int off = 16; off > 0; off >>= 1)
        s += __shfl_xor_sync(0xffffffffu, s, off);
    float ls = logf(s);
    float* orow = out + (size_t)warp * 64;
    orow[lane]      = v0 - m - ls;
    orow[lane + 32] = v1 - m - ls;
}

// ---------------------------------------------------------------------------
// Launch
// ---------------------------------------------------------------------------
extern "C" void kernel_launch(void* const* d_in, const int* in_sizes, int n_in,
                              void* d_out, int out_size) {
    const float* x  = (const float*)d_in[0];
    const int*   ei = (const int*)d_in[1];
    const float* W0 = (const float*)d_in[2];
    const float* b0 = (const float*)d_in[3];
    const float* W1 = (const float*)d_in[4];
    const float* b1 = (const float*)d_in[5];
    const float* W2 = (const float*)d_in[6];
    const float* b2 = (const float*)d_in[7];
    float* out = (float*)d_out;

    const int E = in_sizes[1] / 2;
    const int N = in_sizes[0] / DIM;
    const int* src = ei;
    const int* dst = ei + E;

    float *p_dis, *p_h, *p_a;
    int *p_cnt, *p_rowptr, *p_cursor, *p_colsrc, *p_blocksum;
    __nv_bfloat16 *p_W0h, *p_W0l, *p_W1h, *p_W1l, *p_W2h, *p_W2l;
    cudaGetSymbolAddress((void**)&p_dis,      g_dis);
    cudaGetSymbolAddress((void**)&p_h,        g_h);
    cudaGetSymbolAddress((void**)&p_a,        g_a);
    cudaGetSymbolAddress((void**)&p_cnt,      g_cnt);
    cudaGetSymbolAddress((void**)&p_rowptr,   g_rowptr);
    cudaGetSymbolAddress((void**)&p_cursor,   g_cursor);
    cudaGetSymbolAddress((void**)&p_colsrc,   g_colsrc);
    cudaGetSymbolAddress((void**)&p_blocksum, g_blocksum);
    cudaGetSymbolAddress((void**)&p_W0h, g_W0h); cudaGetSymbolAddress((void**)&p_W0l, g_W0l);
    cudaGetSymbolAddress((void**)&p_W1h, g_W1h); cudaGetSymbolAddress((void**)&p_W1l, g_W1l);
    cudaGetSymbolAddress((void**)&p_W2h, g_W2h); cudaGetSymbolAddress((void**)&p_W2l, g_W2l);

    // One-time resources (host-side objects only; no device memory)
    static cudaStream_t s_prep = nullptr;
    static cudaEvent_t  ev_fork = nullptr, ev_join = nullptr;
    if (s_prep == nullptr) {
        cudaStreamCreateWithFlags(&s_prep, cudaStreamNonBlocking);
        cudaEventCreateWithFlags(&ev_fork, cudaEventDisableTiming);
        cudaEventCreateWithFlags(&ev_join, cudaEventDisableTiming);
    }

    // Dynamic smem sizes for GEMM v2
    const int smem128 = (4 * 128 * 24 + 2 * 128 * 136) * 2;   // 94208 B
    const int smem64  = (4 * 128 * 24 + 2 * 128 * 72)  * 2;   // 61440 B
    cudaFuncSetAttribute(gemm_tc_kernel<128>, cudaFuncAttributeMaxDynamicSharedMemorySize, smem128);
    cudaFuncSetAttribute(gemm_tc_kernel<64>,  cudaFuncAttributeMaxDynamicSharedMemorySize, smem64);

    const int T = 256;
    const int nb = (N + 1023) / 1024;
    const int gemm_blocks = (N + 127) / 128;

    // ---- fork: CSR build on s_prep, concurrent with split_w + gemm0 ----
    cudaEventRecord(ev_fork, 0);
    cudaStreamWaitEvent(s_prep, ev_fork, 0);
    cudaMemsetAsync(p_cnt, 0, (size_t)N * sizeof(int), s_prep);
    count_kernel<<<(E + T - 1) / T, T, 0, s_prep>>>(dst, p_cnt, E);
    scan_block_kernel<<<nb, 1024, 0, s_prep>>>(p_cnt, p_rowptr, p_blocksum, N);
    scan_carry_kernel<<<1, 32, 0, s_prep>>>(p_blocksum, nb);
    scan_add_kernel<<<(N + T - 1) / T, T, 0, s_prep>>>(p_rowptr, p_blocksum, p_cnt,
                                                       p_cursor, p_dis, N, E);
    fill_kernel<<<(E + T - 1) / T, T, 0, s_prep>>>(src, dst, p_cursor, p_colsrc, E);
    cudaEventRecord(ev_join, s_prep);

    // ---- main stream: weight splits + layer 0 GEMM (independent of CSR) ----
    split_w_kernel<<<64, 256>>>(W0, p_W0h, p_W0l, 16384);
    split_w_kernel<<<64, 256>>>(W1, p_W1h, p_W1l, 16384);
    split_w_kernel<<<32, 256>>>(W2, p_W2h, p_W2l, 8192);

    // NOTE: gemm0 reads dis in its epilogue -> dis must be ready. dis is
    // produced by scan_add on s_prep. Join BEFORE gemm0's epilogue need:
    // simplest correct option: join before gemm0.
    cudaStreamWaitEvent(0, ev_join, 0);

    // Layer 0: hs = (x@W0)*dis ; A = relu(dis*segsum + b0)
    gemm_tc_kernel<128><<<gemm_blocks, 256, smem128>>>(x, p_W0h, p_W0l, p_dis, p_h, N);
    agg_combine_kernel<128><<<N, 128>>>(p_h, p_rowptr, p_colsrc, p_dis, b0, p_a, N);

    // Layer 1
    gemm_tc_kernel<128><<<gemm_blocks, 256, smem128>>>(p_a, p_W1h, p_W1l, p_dis, p_h, N);
    agg_combine_kernel<128><<<N, 128>>>(p_h, p_rowptr, p_colsrc, p_dis, b1, p_a, N);

    // Layer 2 (64 cols)
    gemm_tc_kernel<64><<<gemm_blocks, 256, smem64>>>(p_a, p_W2h, p_W2l, p_dis, p_h, N);
    agg_combine_kernel<64><<<N, 64>>>(p_h, p_rowptr, p_colsrc, p_dis, b2, p_a, N);

    // log_softmax
    logsoftmax_kernel<<<(N * 32 + T - 1) / T, T>>>(p_a, out, N);
}